// round 16
// baseline (speedup 1.0000x reference)
#include <cuda_runtime.h>
#include <cuda_bf16.h>
#include <cuda_fp16.h>
#include <cstdint>

#define NN 100000
#define NE 800000
#define GG 782            // gemm CTAs: ceil(NN/128)

// ---------------------------------------------------------------------------
// Device-global scratch
// ---------------------------------------------------------------------------
__device__ __half g_Zh[(size_t)NN * 64];
__device__ float  g_S[(size_t)NN * 64];
__device__ float  g_H1[(size_t)NN * 64];
__device__ float  g_H2[(size_t)NN * 64];
__device__ uint4 g_Bp0[7 * 16 * 8 * 4];
__device__ uint4 g_Bp1[4 * 16 * 8 * 4];
__device__ uint4 g_Bp2[4 * 16 * 8 * 4];
__device__ int g_count[NN];     // starts zero; scan re-zeroes each replay
__device__ int g_off[NN + 1];
__device__ int g_cursor[NN];
__device__ int g_perm[NE];      // stores src*64 (pre-scaled row offset in halves)

// ---------------------------------------------------------------------------
// Weight prep
// ---------------------------------------------------------------------------
__device__ __forceinline__ uint32_t bf2_hi(float x, float y) {
    __nv_bfloat162 p(__float2bfloat16(x), __float2bfloat16(y));
    return *reinterpret_cast<uint32_t*>(&p);
}
__device__ __forceinline__ uint32_t bf2_lo(float x, float y) {
    __nv_bfloat16 hx = __float2bfloat16(x), hy = __float2bfloat16(y);
    __nv_bfloat162 p(__float2bfloat16(x - __bfloat162float(hx)),
                     __float2bfloat16(y - __bfloat162float(hy)));
    return *reinterpret_cast<uint32_t*>(&p);
}
__device__ __forceinline__ float wval(const float* Wn, const float* Ws,
                                      int K, int Nout, int n, int k) {
    if (n < 64) return (n < Nout && k < K) ? Wn[k * Nout + n] : 0.f;
    int m = n - 64;
    return (m < Nout && k < K) ? Ws[k * Nout + m] : 0.f;
}
__global__ void wprep_packed(const float* __restrict__ Wn0, const float* __restrict__ Ws0,
                             const float* __restrict__ Wn1, const float* __restrict__ Ws1,
                             const float* __restrict__ Wn2, const float* __restrict__ Ws2) {
    int b = blockIdx.x, tid = threadIdx.x;
    const float *Wn, *Ws;
    uint4* Bp;
    int K, Nout, total, idx;
    if (b < 14)      { Wn = Wn0; Ws = Ws0; Bp = g_Bp0; K = 100; Nout = 64; total = 7 * 512; idx = b * 256 + tid; }
    else if (b < 22) { Wn = Wn1; Ws = Ws1; Bp = g_Bp1; K = 64;  Nout = 64; total = 4 * 512; idx = (b - 14) * 256 + tid; }
    else             { Wn = Wn2; Ws = Ws2; Bp = g_Bp2; K = 64;  Nout = 47; total = 4 * 512; idx = (b - 22) * 256 + tid; }
    if (idx >= total) return;
    int q  = idx & 3;
    int g  = (idx >> 2) & 7;
    int nt = (idx >> 5) & 15;
    int ks = idx >> 9;
    int n  = nt * 8 + g;
    int k1 = ks * 16 + 2 * q;
    int k2 = k1 + 8;
    float v0 = wval(Wn, Ws, K, Nout, n, k1);
    float v1 = wval(Wn, Ws, K, Nout, n, k1 + 1);
    float v2 = wval(Wn, Ws, K, Nout, n, k2);
    float v3 = wval(Wn, Ws, K, Nout, n, k2 + 1);
    uint4 o;
    o.x = bf2_hi(v0, v1);
    o.y = bf2_hi(v2, v3);
    o.z = bf2_lo(v0, v1);
    o.w = bf2_lo(v2, v3);
    Bp[idx] = o;
}

// ---------------------------------------------------------------------------
// CSR build: count -> scan (zeroes count) -> fill (pre-scaled perm)
// ---------------------------------------------------------------------------
__global__ void count_kernel(const int* __restrict__ dst) {
    int e = blockIdx.x * blockDim.x + threadIdx.x;
    if (e < NE) atomicAdd(&g_count[dst[e]], 1);
}
__global__ void scan_kernel() {
    __shared__ int part[1024];
    const int C = (NN + 1023) / 1024;
    int t = threadIdx.x, base = t * C, s = 0;
    for (int i = 0; i < C; ++i) { int idx = base + i; if (idx < NN) s += g_count[idx]; }
    part[t] = s;
    __syncthreads();
    for (int o = 1; o < 1024; o <<= 1) {
        int v = (t >= o) ? part[t - o] : 0;
        __syncthreads();
        part[t] += v;
        __syncthreads();
    }
    int run = (t > 0) ? part[t - 1] : 0;
    for (int i = 0; i < C; ++i) {
        int idx = base + i;
        if (idx < NN) {
            int c = g_count[idx];
            g_count[idx] = 0;
            g_off[idx] = run;
            g_cursor[idx] = run;
            run += c;
        }
    }
    if (t == 0) g_off[NN] = part[1023];
}
__global__ void fill_kernel(const int* __restrict__ src, const int* __restrict__ dst) {
    int e = blockIdx.x * blockDim.x + threadIdx.x;
    if (e < NE) {
        int p = atomicAdd(&g_cursor[dst[e]], 1);
        g_perm[p] = src[e] * 64;    // pre-scaled row offset (halves)
    }
}

// ---------------------------------------------------------------------------
// GEMM: ldmatrix A (bf16 hi/lo), packed-fragment B, 3-term split, two-pass
// N-split. NTZ/NTS = tiles per half (layer 2 trims to 6/6 = cols 0-47).
// ---------------------------------------------------------------------------
__device__ __forceinline__ void mma16816(float c[4], const uint32_t a[4],
                                         uint32_t b0, uint32_t b1) {
    asm volatile(
        "mma.sync.aligned.m16n8k16.row.col.f32.bf16.bf16.f32 "
        "{%0,%1,%2,%3}, {%4,%5,%6,%7}, {%8,%9}, {%0,%1,%2,%3};"
        : "+f"(c[0]), "+f"(c[1]), "+f"(c[2]), "+f"(c[3])
        : "r"(a[0]), "r"(a[1]), "r"(a[2]), "r"(a[3]), "r"(b0), "r"(b1));
}
__device__ __forceinline__ void ldsm_x4(uint32_t r[4], uint32_t addr) {
    asm volatile("ldmatrix.sync.aligned.m8n8.x4.shared.b16 {%0,%1,%2,%3}, [%4];"
                 : "=r"(r[0]), "=r"(r[1]), "=r"(r[2]), "=r"(r[3]) : "r"(addr));
}
__device__ __forceinline__ uint32_t smem_u32(const void* p) {
    uint32_t a;
    asm("{ .reg .u64 t; cvta.to.shared.u64 t, %1; cvt.u32.u64 %0, t; }" : "=r"(a) : "l"(p));
    return a;
}

template <int K, int KPAD, int HS, int NTZ, int NTS>
__global__ __launch_bounds__(256, 3) void gemm_mma(
    const float* __restrict__ H, const uint4* __restrict__ Bp,
    __half* __restrict__ Zh, float* __restrict__ S) {
    constexpr int KSTEPS = KPAD / 16;
    constexpr int KPADS = KPAD + 8;
    extern __shared__ char smraw[];
    __nv_bfloat16* shi = reinterpret_cast<__nv_bfloat16*>(smraw);
    __nv_bfloat16* slo = shi + 128 * KPADS;

    int tid = threadIdx.x;
    int w = tid >> 5, lane = tid & 31;
    int g = lane >> 2, q = lane & 3;
    int t = lane >> 3, r = lane & 7;
    int rowBase = blockIdx.x * 128;

    constexpr int C4 = KPAD / 4;
    for (int i = tid; i < 128 * C4; i += 256) {
        int row = i / C4, col = (i - row * C4) * 4;
        int rg = rowBase + row; if (rg >= NN) rg = NN - 1;
        float4 v;
        if (col + 4 <= K) v = *(const float4*)(H + (size_t)rg * HS + col);
        else v = make_float4(0.f, 0.f, 0.f, 0.f);
        uint2 hw = {bf2_hi(v.x, v.y), bf2_hi(v.z, v.w)};
        uint2 lw = {bf2_lo(v.x, v.y), bf2_lo(v.z, v.w)};
        *(uint2*)(shi + row * KPADS + col) = hw;
        *(uint2*)(slo + row * KPADS + col) = lw;
    }
    __syncthreads();

    int arow = w * 16 + (t & 1) * 8 + r;
    int acol0 = (t >> 1) * 8;
    uint32_t hi_addr = smem_u32(shi + arow * KPADS + acol0);
    uint32_t lo_addr = smem_u32(slo + arow * KPADS + acol0);

    int rr0 = rowBase + w * 16 + g;
    int rr1 = rr0 + 8;

    #pragma unroll
    for (int half = 0; half < 2; ++half) {
        constexpr int NTMAX = (NTZ > NTS) ? NTZ : NTS;
        const int NT = (half == 0) ? NTZ : NTS;
        float acc[NTMAX][4];
        #pragma unroll
        for (int nt = 0; nt < NTMAX; ++nt)
            #pragma unroll
            for (int j = 0; j < 4; ++j) acc[nt][j] = 0.f;

        #pragma unroll
        for (int ks = 0; ks < KSTEPS; ++ks) {
            uint32_t ahi[4], alo[4];
            ldsm_x4(ahi, hi_addr + ks * 32);
            ldsm_x4(alo, lo_addr + ks * 32);
            const uint4* bp = Bp + ((size_t)ks * 16 * 32) + (half * 8) * 32 + g * 4 + q;
            #pragma unroll
            for (int nt = 0; nt < NTMAX; ++nt) {
                if (nt >= NT) break;
                uint4 b = __ldg(bp + nt * 32);
                mma16816(acc[nt], ahi, b.x, b.y);
                mma16816(acc[nt], ahi, b.z, b.w);
                mma16816(acc[nt], alo, b.x, b.y);
            }
        }

        if (half == 0) {
            #pragma unroll
            for (int nt = 0; nt < NTMAX; ++nt) {
                if (nt >= NT) break;
                int col = nt * 8 + 2 * q;
                if (rr0 < NN) *(__half2*)(Zh + (size_t)rr0 * 64 + col) =
                    __floats2half2_rn(acc[nt][0], acc[nt][1]);
                if (rr1 < NN) *(__half2*)(Zh + (size_t)rr1 * 64 + col) =
                    __floats2half2_rn(acc[nt][2], acc[nt][3]);
            }
        } else {
            #pragma unroll
            for (int nt = 0; nt < NTMAX; ++nt) {
                if (nt >= NT) break;
                int col = nt * 8 + 2 * q;
                if (rr0 < NN) *(float2*)(S + (size_t)rr0 * 64 + col) = make_float2(acc[nt][0], acc[nt][1]);
                if (rr1 < NN) *(float2*)(S + (size_t)rr1 * 64 + col) = make_float2(acc[nt][2], acc[nt][3]);
            }
        }
    }
}

// ---------------------------------------------------------------------------
// Gather (R12 measured-good form; pre-scaled perm): 16 threads/node,
// 8-wide unroll + serial remainder.  relu(S + sum/deg + bias)
// ---------------------------------------------------------------------------
__device__ __forceinline__ void acc_u2(float4& a, uint2 u) {
    __half2* p = reinterpret_cast<__half2*>(&u);
    float2 f0 = __half22float2(p[0]);
    float2 f1 = __half22float2(p[1]);
    a.x += f0.x; a.y += f0.y; a.z += f1.x; a.w += f1.y;
}
__device__ __forceinline__ float4 gather_node(const __half* __restrict__ Zh,
                                              int node, int tx) {
    int s = g_off[node], e = g_off[node + 1];
    const __half* Zc = Zh + tx * 4;
    float4 a0 = make_float4(0.f, 0.f, 0.f, 0.f);
    float4 a1 = a0;
    int j = s;
    for (; j + 8 <= e; j += 8) {
        int r0 = g_perm[j],     r1 = g_perm[j + 1], r2 = g_perm[j + 2], r3 = g_perm[j + 3];
        int r4 = g_perm[j + 4], r5 = g_perm[j + 5], r6 = g_perm[j + 6], r7 = g_perm[j + 7];
        uint2 u0 = *(const uint2*)(Zc + (size_t)r0);
        uint2 u1 = *(const uint2*)(Zc + (size_t)r1);
        uint2 u2 = *(const uint2*)(Zc + (size_t)r2);
        uint2 u3 = *(const uint2*)(Zc + (size_t)r3);
        uint2 u4 = *(const uint2*)(Zc + (size_t)r4);
        uint2 u5 = *(const uint2*)(Zc + (size_t)r5);
        uint2 u6 = *(const uint2*)(Zc + (size_t)r6);
        uint2 u7 = *(const uint2*)(Zc + (size_t)r7);
        acc_u2(a0, u0); acc_u2(a0, u1); acc_u2(a0, u2); acc_u2(a0, u3);
        acc_u2(a1, u4); acc_u2(a1, u5); acc_u2(a1, u6); acc_u2(a1, u7);
    }
    for (; j < e; ++j) {
        uint2 u = *(const uint2*)(Zc + (size_t)g_perm[j]);
        acc_u2(a0, u);
    }
    return make_float4(a0.x + a1.x, a0.y + a1.y, a0.z + a1.z, a0.w + a1.w);
}

__global__ void gather_epi_mid(const __half* __restrict__ Zh, const float* __restrict__ S,
                               const float* __restrict__ bias, float* __restrict__ Hout) {
    int node = blockIdx.x * 16 + threadIdx.y;
    if (node >= NN) return;
    int tx = threadIdx.x;
    float4 acc = gather_node(Zh, node, tx);
    float inv = 1.0f / fmaxf((float)(g_off[node + 1] - g_off[node]), 1.0f);
    float4 sv = *(const float4*)(S + (size_t)node * 64 + tx * 4);
    float4 bv = *(const float4*)(bias + tx * 4);
    float4 o = make_float4(fmaxf(sv.x + acc.x * inv + bv.x, 0.f),
                           fmaxf(sv.y + acc.y * inv + bv.y, 0.f),
                           fmaxf(sv.z + acc.z * inv + bv.z, 0.f),
                           fmaxf(sv.w + acc.w * inv + bv.w, 0.f));
    *(float4*)(Hout + (size_t)node * 64 + tx * 4) = o;
}

__global__ void gather_epi_out(const __half* __restrict__ Zh, const float* __restrict__ S,
                               const float* __restrict__ bias, float* __restrict__ out) {
    int node = blockIdx.x * 16 + threadIdx.y;
    if (node >= NN) return;
    int tx = threadIdx.x;  // 0..11 -> cols 0..47
    float4 acc = gather_node(Zh, node, tx);
    float inv = 1.0f / fmaxf((float)(g_off[node + 1] - g_off[node]), 1.0f);
    float4 sv = *(const float4*)(S + (size_t)node * 64 + tx * 4);
    float a[4] = {acc.x, acc.y, acc.z, acc.w};
    float s[4] = {sv.x, sv.y, sv.z, sv.w};
    #pragma unroll
    for (int j = 0; j < 4; ++j) {
        int c = tx * 4 + j;
        if (c < 47) out[(size_t)node * 47 + c] = s[j] + a[j] * inv + bias[c];
    }
}

// ---------------------------------------------------------------------------
// Launch: two-stream fork-join.
// streamA(0): wprep -> gemm0 ; streamB: count -> scan -> fill ; join -> rest.
// API kernel order: #1 wprep, #2 count, #3 gemm0, #4 scan (ncu window), #5 fill.
// ---------------------------------------------------------------------------
extern "C" void kernel_launch(void* const* d_in, const int* in_sizes, int n_in,
                              void* d_out, int out_size) {
    const float* x    = (const float*)d_in[0];
    const int*   esrc = (const int*)d_in[1];
    const int*   edst = (const int*)d_in[2];
    const float* Ws0  = (const float*)d_in[3];
    const float* Wn0  = (const float*)d_in[4];
    const float* b0   = (const float*)d_in[5];
    const float* Ws1  = (const float*)d_in[6];
    const float* Wn1  = (const float*)d_in[7];
    const float* b1   = (const float*)d_in[8];
    const float* Ws2  = (const float*)d_in[9];
    const float* Wn2  = (const float*)d_in[10];
    const float* b2   = (const float*)d_in[11];
    float*       out  = (float*)d_out;

    void *p_Zh, *p_S, *p_H1, *p_H2, *p_Bp0, *p_Bp1, *p_Bp2;
    cudaGetSymbolAddress(&p_Zh, g_Zh);
    cudaGetSymbolAddress(&p_S, g_S);
    cudaGetSymbolAddress(&p_H1, g_H1);
    cudaGetSymbolAddress(&p_H2, g_H2);
    cudaGetSymbolAddress(&p_Bp0, g_Bp0);
    cudaGetSymbolAddress(&p_Bp1, g_Bp1);
    cudaGetSymbolAddress(&p_Bp2, g_Bp2);
    __half* Zh = (__half*)p_Zh;
    float* S  = (float*)p_S;
    float* H1 = (float*)p_H1;
    float* H2 = (float*)p_H2;

    cudaFuncSetAttribute((void*)gemm_mma<100, 112, 100, 8, 8>,
                         cudaFuncAttributeMaxDynamicSharedMemorySize, 61440);
    cudaFuncSetAttribute((void*)gemm_mma<64, 64, 64, 8, 8>,
                         cudaFuncAttributeMaxDynamicSharedMemorySize, 36864);
    cudaFuncSetAttribute((void*)gemm_mma<64, 64, 64, 6, 6>,
                         cudaFuncAttributeMaxDynamicSharedMemorySize, 36864);

    const int TB = 256;
    const int EGk = (NE + TB - 1) / TB;
    const int NG = (NN + 15) / 16;

    cudaStream_t s2;
    cudaEvent_t evFork, evJoin;
    cudaStreamCreateWithFlags(&s2, cudaStreamNonBlocking);
    cudaEventCreateWithFlags(&evFork, cudaEventDisableTiming);
    cudaEventCreateWithFlags(&evJoin, cudaEventDisableTiming);

    cudaEventRecord(evFork, 0);
    cudaStreamWaitEvent(s2, evFork, 0);

    wprep_packed<<<30, 256>>>(Wn0, Ws0, Wn1, Ws1, Wn2, Ws2);                 // #1 (A)
    count_kernel<<<EGk, TB, 0, s2>>>(edst);                                  // #2 (B)
    gemm_mma<100, 112, 100, 8, 8><<<GG, 256, 61440>>>(x, (const uint4*)p_Bp0, Zh, S);  // #3 (A)
    scan_kernel<<<1, 1024, 0, s2>>>();                                       // #4 (B) <- ncu
    fill_kernel<<<EGk, TB, 0, s2>>>(esrc, edst);                             // #5 (B)
    cudaEventRecord(evJoin, s2);
    cudaStreamWaitEvent(0, evJoin, 0);

    gather_epi_mid<<<NG, dim3(16, 16)>>>(Zh, S, b0, H1);                     // #6
    gemm_mma<64, 64, 64, 8, 8><<<GG, 256, 36864>>>(H1, (const uint4*)p_Bp1, Zh, S);    // #7
    gather_epi_mid<<<NG, dim3(16, 16)>>>(Zh, S, b1, H2);                     // #8
    gemm_mma<64, 64, 64, 6, 6><<<GG, 256, 36864>>>(H2, (const uint4*)p_Bp2, Zh, S);    // #9
    gather_epi_out<<<NG, dim3(12, 16)>>>(Zh, S, b2, out);                    // #10
    // s2/events intentionally not destroyed (graph capture holds references).
}

// round 17
// speedup vs baseline: 2.7242x; 2.7242x over previous
#include <cuda_runtime.h>
#include <cuda_bf16.h>
#include <cuda_fp16.h>
#include <cstdint>

#define NN 100000
#define NE 800000
#define GG 782            // gemm CTAs: ceil(NN/128)
#define NB 98             // scan blocks: ceil(NN/1024)

// ---------------------------------------------------------------------------
// Device-global scratch
// ---------------------------------------------------------------------------
__device__ __half g_Zh[(size_t)NN * 64];
__device__ float  g_S[(size_t)NN * 64];
__device__ float  g_H1[(size_t)NN * 64];
__device__ float  g_H2[(size_t)NN * 64];
__device__ uint4 g_Bp0[7 * 16 * 8 * 4];
__device__ uint4 g_Bp1[4 * 16 * 8 * 4];
__device__ uint4 g_Bp2[4 * 16 * 8 * 4];
__device__ int g_count[NN];     // starts zero; scan_fix re-zeroes each replay
__device__ int g_bsum[NB];
__device__ int g_off[NN + 1];
__device__ int g_cursor[NN];
__device__ int g_perm[NE];      // stores src*64 (pre-scaled row offset in halves)

// ---------------------------------------------------------------------------
// Weight prep
// ---------------------------------------------------------------------------
__device__ __forceinline__ uint32_t bf2_hi(float x, float y) {
    __nv_bfloat162 p(__float2bfloat16(x), __float2bfloat16(y));
    return *reinterpret_cast<uint32_t*>(&p);
}
__device__ __forceinline__ uint32_t bf2_lo(float x, float y) {
    __nv_bfloat16 hx = __float2bfloat16(x), hy = __float2bfloat16(y);
    __nv_bfloat162 p(__float2bfloat16(x - __bfloat162float(hx)),
                     __float2bfloat16(y - __bfloat162float(hy)));
    return *reinterpret_cast<uint32_t*>(&p);
}
__device__ __forceinline__ float wval(const float* Wn, const float* Ws,
                                      int K, int Nout, int n, int k) {
    if (n < 64) return (n < Nout && k < K) ? Wn[k * Nout + n] : 0.f;
    int m = n - 64;
    return (m < Nout && k < K) ? Ws[k * Nout + m] : 0.f;
}
__global__ void wprep_packed(const float* __restrict__ Wn0, const float* __restrict__ Ws0,
                             const float* __restrict__ Wn1, const float* __restrict__ Ws1,
                             const float* __restrict__ Wn2, const float* __restrict__ Ws2) {
    int b = blockIdx.x, tid = threadIdx.x;
    const float *Wn, *Ws;
    uint4* Bp;
    int K, Nout, total, idx;
    if (b < 14)      { Wn = Wn0; Ws = Ws0; Bp = g_Bp0; K = 100; Nout = 64; total = 7 * 512; idx = b * 256 + tid; }
    else if (b < 22) { Wn = Wn1; Ws = Ws1; Bp = g_Bp1; K = 64;  Nout = 64; total = 4 * 512; idx = (b - 14) * 256 + tid; }
    else             { Wn = Wn2; Ws = Ws2; Bp = g_Bp2; K = 64;  Nout = 47; total = 4 * 512; idx = (b - 22) * 256 + tid; }
    if (idx >= total) return;
    int q  = idx & 3;
    int g  = (idx >> 2) & 7;
    int nt = (idx >> 5) & 15;
    int ks = idx >> 9;
    int n  = nt * 8 + g;
    int k1 = ks * 16 + 2 * q;
    int k2 = k1 + 8;
    float v0 = wval(Wn, Ws, K, Nout, n, k1);
    float v1 = wval(Wn, Ws, K, Nout, n, k1 + 1);
    float v2 = wval(Wn, Ws, K, Nout, n, k2);
    float v3 = wval(Wn, Ws, K, Nout, n, k2 + 1);
    uint4 o;
    o.x = bf2_hi(v0, v1);
    o.y = bf2_hi(v2, v3);
    o.z = bf2_lo(v0, v1);
    o.w = bf2_lo(v2, v3);
    Bp[idx] = o;
}

// ---------------------------------------------------------------------------
// CSR build: count -> scan_local + scan_fix (parallel prefix) -> fill
// ---------------------------------------------------------------------------
__global__ void count_kernel(const int* __restrict__ dst) {
    int e = blockIdx.x * blockDim.x + threadIdx.x;
    if (e < NE) atomicAdd(&g_count[dst[e]], 1);
}

// 98 blocks x 1024: block-local exclusive prefix into g_off, block sums to g_bsum
__global__ void scan_local() {
    __shared__ int sm[1024];
    int b = blockIdx.x, t = threadIdx.x;
    int node = b * 1024 + t;
    int c = (node < NN) ? g_count[node] : 0;
    sm[t] = c;
    __syncthreads();
    for (int o = 1; o < 1024; o <<= 1) {
        int v = (t >= o) ? sm[t - o] : 0;
        __syncthreads();
        sm[t] += v;
        __syncthreads();
    }
    if (node < NN) g_off[node] = sm[t] - c;   // local exclusive prefix
    if (t == 1023) g_bsum[b] = sm[t];
}

// 98 blocks x 1024: add block base, write cursor, zero count, write off[NN]
__global__ void scan_fix() {
    __shared__ int sb[NB];
    int b = blockIdx.x, t = threadIdx.x;
    if (t < NB) sb[t] = g_bsum[t];
    __syncthreads();
    int base = 0;
    for (int j = 0; j < b; ++j) base += sb[j];
    int node = b * 1024 + t;
    if (node < NN) {
        int v = g_off[node] + base;
        g_off[node] = v;
        g_cursor[node] = v;
        g_count[node] = 0;           // ready for next replay (no memset launch)
    }
    if (b == NB - 1 && t == 0) g_off[NN] = base + sb[NB - 1];
}

__global__ void fill_kernel(const int* __restrict__ src, const int* __restrict__ dst) {
    int e = blockIdx.x * blockDim.x + threadIdx.x;
    if (e < NE) {
        int p = atomicAdd(&g_cursor[dst[e]], 1);
        g_perm[p] = src[e] * 64;    // pre-scaled row offset (halves)
    }
}

// ---------------------------------------------------------------------------
// GEMM: ldmatrix A (bf16 hi/lo), packed-fragment B, 3-term split, two-pass
// N-split. NTZ/NTS = tiles per half (layer 2 trims to 6/6 = cols 0-47).
// ---------------------------------------------------------------------------
__device__ __forceinline__ void mma16816(float c[4], const uint32_t a[4],
                                         uint32_t b0, uint32_t b1) {
    asm volatile(
        "mma.sync.aligned.m16n8k16.row.col.f32.bf16.bf16.f32 "
        "{%0,%1,%2,%3}, {%4,%5,%6,%7}, {%8,%9}, {%0,%1,%2,%3};"
        : "+f"(c[0]), "+f"(c[1]), "+f"(c[2]), "+f"(c[3])
        : "r"(a[0]), "r"(a[1]), "r"(a[2]), "r"(a[3]), "r"(b0), "r"(b1));
}
__device__ __forceinline__ void ldsm_x4(uint32_t r[4], uint32_t addr) {
    asm volatile("ldmatrix.sync.aligned.m8n8.x4.shared.b16 {%0,%1,%2,%3}, [%4];"
                 : "=r"(r[0]), "=r"(r[1]), "=r"(r[2]), "=r"(r[3]) : "r"(addr));
}
__device__ __forceinline__ uint32_t smem_u32(const void* p) {
    uint32_t a;
    asm("{ .reg .u64 t; cvta.to.shared.u64 t, %1; cvt.u32.u64 %0, t; }" : "=r"(a) : "l"(p));
    return a;
}

template <int K, int KPAD, int HS, int NTZ, int NTS>
__global__ __launch_bounds__(256, 3) void gemm_mma(
    const float* __restrict__ H, const uint4* __restrict__ Bp,
    __half* __restrict__ Zh, float* __restrict__ S) {
    constexpr int KSTEPS = KPAD / 16;
    constexpr int KPADS = KPAD + 8;
    extern __shared__ char smraw[];
    __nv_bfloat16* shi = reinterpret_cast<__nv_bfloat16*>(smraw);
    __nv_bfloat16* slo = shi + 128 * KPADS;

    int tid = threadIdx.x;
    int w = tid >> 5, lane = tid & 31;
    int g = lane >> 2, q = lane & 3;
    int t = lane >> 3, r = lane & 7;
    int rowBase = blockIdx.x * 128;

    constexpr int C4 = KPAD / 4;
    for (int i = tid; i < 128 * C4; i += 256) {
        int row = i / C4, col = (i - row * C4) * 4;
        int rg = rowBase + row; if (rg >= NN) rg = NN - 1;
        float4 v;
        if (col + 4 <= K) v = *(const float4*)(H + (size_t)rg * HS + col);
        else v = make_float4(0.f, 0.f, 0.f, 0.f);
        uint2 hw = {bf2_hi(v.x, v.y), bf2_hi(v.z, v.w)};
        uint2 lw = {bf2_lo(v.x, v.y), bf2_lo(v.z, v.w)};
        *(uint2*)(shi + row * KPADS + col) = hw;
        *(uint2*)(slo + row * KPADS + col) = lw;
    }
    __syncthreads();

    int arow = w * 16 + (t & 1) * 8 + r;
    int acol0 = (t >> 1) * 8;
    uint32_t hi_addr = smem_u32(shi + arow * KPADS + acol0);
    uint32_t lo_addr = smem_u32(slo + arow * KPADS + acol0);

    int rr0 = rowBase + w * 16 + g;
    int rr1 = rr0 + 8;

    #pragma unroll
    for (int half = 0; half < 2; ++half) {
        constexpr int NTMAX = (NTZ > NTS) ? NTZ : NTS;
        const int NT = (half == 0) ? NTZ : NTS;
        float acc[NTMAX][4];
        #pragma unroll
        for (int nt = 0; nt < NTMAX; ++nt)
            #pragma unroll
            for (int j = 0; j < 4; ++j) acc[nt][j] = 0.f;

        #pragma unroll
        for (int ks = 0; ks < KSTEPS; ++ks) {
            uint32_t ahi[4], alo[4];
            ldsm_x4(ahi, hi_addr + ks * 32);
            ldsm_x4(alo, lo_addr + ks * 32);
            const uint4* bp = Bp + ((size_t)ks * 16 * 32) + (half * 8) * 32 + g * 4 + q;
            #pragma unroll
            for (int nt = 0; nt < NTMAX; ++nt) {
                if (nt >= NT) break;
                uint4 b = __ldg(bp + nt * 32);
                mma16816(acc[nt], ahi, b.x, b.y);
                mma16816(acc[nt], ahi, b.z, b.w);
                mma16816(acc[nt], alo, b.x, b.y);
            }
        }

        if (half == 0) {
            #pragma unroll
            for (int nt = 0; nt < NTMAX; ++nt) {
                if (nt >= NT) break;
                int col = nt * 8 + 2 * q;
                if (rr0 < NN) *(__half2*)(Zh + (size_t)rr0 * 64 + col) =
                    __floats2half2_rn(acc[nt][0], acc[nt][1]);
                if (rr1 < NN) *(__half2*)(Zh + (size_t)rr1 * 64 + col) =
                    __floats2half2_rn(acc[nt][2], acc[nt][3]);
            }
        } else {
            #pragma unroll
            for (int nt = 0; nt < NTMAX; ++nt) {
                if (nt >= NT) break;
                int col = nt * 8 + 2 * q;
                if (rr0 < NN) *(float2*)(S + (size_t)rr0 * 64 + col) = make_float2(acc[nt][0], acc[nt][1]);
                if (rr1 < NN) *(float2*)(S + (size_t)rr1 * 64 + col) = make_float2(acc[nt][2], acc[nt][3]);
            }
        }
    }
}

// ---------------------------------------------------------------------------
// Gather (R12 measured-good form; pre-scaled perm): 16 threads/node,
// 8-wide unroll + serial remainder.  relu(S + sum/deg + bias)
// ---------------------------------------------------------------------------
__device__ __forceinline__ void acc_u2(float4& a, uint2 u) {
    __half2* p = reinterpret_cast<__half2*>(&u);
    float2 f0 = __half22float2(p[0]);
    float2 f1 = __half22float2(p[1]);
    a.x += f0.x; a.y += f0.y; a.z += f1.x; a.w += f1.y;
}
__device__ __forceinline__ float4 gather_node(const __half* __restrict__ Zh,
                                              int node, int tx) {
    int s = g_off[node], e = g_off[node + 1];
    const __half* Zc = Zh + tx * 4;
    float4 a0 = make_float4(0.f, 0.f, 0.f, 0.f);
    float4 a1 = a0;
    int j = s;
    for (; j + 8 <= e; j += 8) {
        int r0 = g_perm[j],     r1 = g_perm[j + 1], r2 = g_perm[j + 2], r3 = g_perm[j + 3];
        int r4 = g_perm[j + 4], r5 = g_perm[j + 5], r6 = g_perm[j + 6], r7 = g_perm[j + 7];
        uint2 u0 = *(const uint2*)(Zc + (size_t)r0);
        uint2 u1 = *(const uint2*)(Zc + (size_t)r1);
        uint2 u2 = *(const uint2*)(Zc + (size_t)r2);
        uint2 u3 = *(const uint2*)(Zc + (size_t)r3);
        uint2 u4 = *(const uint2*)(Zc + (size_t)r4);
        uint2 u5 = *(const uint2*)(Zc + (size_t)r5);
        uint2 u6 = *(const uint2*)(Zc + (size_t)r6);
        uint2 u7 = *(const uint2*)(Zc + (size_t)r7);
        acc_u2(a0, u0); acc_u2(a0, u1); acc_u2(a0, u2); acc_u2(a0, u3);
        acc_u2(a1, u4); acc_u2(a1, u5); acc_u2(a1, u6); acc_u2(a1, u7);
    }
    for (; j < e; ++j) {
        uint2 u = *(const uint2*)(Zc + (size_t)g_perm[j]);
        acc_u2(a0, u);
    }
    return make_float4(a0.x + a1.x, a0.y + a1.y, a0.z + a1.z, a0.w + a1.w);
}

__global__ void gather_epi_mid(const __half* __restrict__ Zh, const float* __restrict__ S,
                               const float* __restrict__ bias, float* __restrict__ Hout) {
    int node = blockIdx.x * 16 + threadIdx.y;
    if (node >= NN) return;
    int tx = threadIdx.x;
    float4 acc = gather_node(Zh, node, tx);
    float inv = 1.0f / fmaxf((float)(g_off[node + 1] - g_off[node]), 1.0f);
    float4 sv = *(const float4*)(S + (size_t)node * 64 + tx * 4);
    float4 bv = *(const float4*)(bias + tx * 4);
    float4 o = make_float4(fmaxf(sv.x + acc.x * inv + bv.x, 0.f),
                           fmaxf(sv.y + acc.y * inv + bv.y, 0.f),
                           fmaxf(sv.z + acc.z * inv + bv.z, 0.f),
                           fmaxf(sv.w + acc.w * inv + bv.w, 0.f));
    *(float4*)(Hout + (size_t)node * 64 + tx * 4) = o;
}

__global__ void gather_epi_out(const __half* __restrict__ Zh, const float* __restrict__ S,
                               const float* __restrict__ bias, float* __restrict__ out) {
    int node = blockIdx.x * 16 + threadIdx.y;
    if (node >= NN) return;
    int tx = threadIdx.x;  // 0..11 -> cols 0..47
    float4 acc = gather_node(Zh, node, tx);
    float inv = 1.0f / fmaxf((float)(g_off[node + 1] - g_off[node]), 1.0f);
    float4 sv = *(const float4*)(S + (size_t)node * 64 + tx * 4);
    float a[4] = {acc.x, acc.y, acc.z, acc.w};
    float s[4] = {sv.x, sv.y, sv.z, sv.w};
    #pragma unroll
    for (int j = 0; j < 4; ++j) {
        int c = tx * 4 + j;
        if (c < 47) out[(size_t)node * 47 + c] = s[j] + a[j] * inv + bias[c];
    }
}

// ---------------------------------------------------------------------------
// Launch: two-stream fork-join.
// streamA(0): wprep -> gemm0 ; streamB: count -> scan_local -> scan_fix -> fill
// API kernel order: #1 wprep, #2 count, #3 gemm0, #4 scan_local (ncu), #5 scan_fix, #6 fill.
// ---------------------------------------------------------------------------
extern "C" void kernel_launch(void* const* d_in, const int* in_sizes, int n_in,
                              void* d_out, int out_size) {
    const float* x    = (const float*)d_in[0];
    const int*   esrc = (const int*)d_in[1];
    const int*   edst = (const int*)d_in[2];
    const float* Ws0  = (const float*)d_in[3];
    const float* Wn0  = (const float*)d_in[4];
    const float* b0   = (const float*)d_in[5];
    const float* Ws1  = (const float*)d_in[6];
    const float* Wn1  = (const float*)d_in[7];
    const float* b1   = (const float*)d_in[8];
    const float* Ws2  = (const float*)d_in[9];
    const float* Wn2  = (const float*)d_in[10];
    const float* b2   = (const float*)d_in[11];
    float*       out  = (float*)d_out;

    void *p_Zh, *p_S, *p_H1, *p_H2, *p_Bp0, *p_Bp1, *p_Bp2;
    cudaGetSymbolAddress(&p_Zh, g_Zh);
    cudaGetSymbolAddress(&p_S, g_S);
    cudaGetSymbolAddress(&p_H1, g_H1);
    cudaGetSymbolAddress(&p_H2, g_H2);
    cudaGetSymbolAddress(&p_Bp0, g_Bp0);
    cudaGetSymbolAddress(&p_Bp1, g_Bp1);
    cudaGetSymbolAddress(&p_Bp2, g_Bp2);
    __half* Zh = (__half*)p_Zh;
    float* S  = (float*)p_S;
    float* H1 = (float*)p_H1;
    float* H2 = (float*)p_H2;

    cudaFuncSetAttribute((void*)gemm_mma<100, 112, 100, 8, 8>,
                         cudaFuncAttributeMaxDynamicSharedMemorySize, 61440);
    cudaFuncSetAttribute((void*)gemm_mma<64, 64, 64, 8, 8>,
                         cudaFuncAttributeMaxDynamicSharedMemorySize, 36864);
    cudaFuncSetAttribute((void*)gemm_mma<64, 64, 64, 6, 6>,
                         cudaFuncAttributeMaxDynamicSharedMemorySize, 36864);

    const int TB = 256;
    const int EGk = (NE + TB - 1) / TB;
    const int NG = (NN + 15) / 16;

    cudaStream_t s2;
    cudaEvent_t evFork, evJoin;
    cudaStreamCreateWithFlags(&s2, cudaStreamNonBlocking);
    cudaEventCreateWithFlags(&evFork, cudaEventDisableTiming);
    cudaEventCreateWithFlags(&evJoin, cudaEventDisableTiming);

    cudaEventRecord(evFork, 0);
    cudaStreamWaitEvent(s2, evFork, 0);

    wprep_packed<<<30, 256>>>(Wn0, Ws0, Wn1, Ws1, Wn2, Ws2);                 // #1 (A)
    count_kernel<<<EGk, TB, 0, s2>>>(edst);                                  // #2 (B)
    gemm_mma<100, 112, 100, 8, 8><<<GG, 256, 61440>>>(x, (const uint4*)p_Bp0, Zh, S);  // #3 (A)
    scan_local<<<NB, 1024, 0, s2>>>();                                       // #4 (B) <- ncu
    scan_fix<<<NB, 1024, 0, s2>>>();                                         // #5 (B)
    fill_kernel<<<EGk, TB, 0, s2>>>(esrc, edst);                             // #6 (B)
    cudaEventRecord(evJoin, s2);
    cudaStreamWaitEvent(0, evJoin, 0);

    gather_epi_mid<<<NG, dim3(16, 16)>>>(Zh, S, b0, H1);                     // #7
    gemm_mma<64, 64, 64, 8, 8><<<GG, 256, 36864>>>(H1, (const uint4*)p_Bp1, Zh, S);    // #8
    gather_epi_mid<<<NG, dim3(16, 16)>>>(Zh, S, b1, H2);                     // #9
    gemm_mma<64, 64, 64, 6, 6><<<GG, 256, 36864>>>(H2, (const uint4*)p_Bp2, Zh, S);    // #10
    gather_epi_out<<<NG, dim3(12, 16)>>>(Zh, S, b2, out);                    // #11
    // s2/events intentionally not destroyed (graph capture holds references).
}